// round 15
// baseline (speedup 1.0000x reference)
#include <cuda_runtime.h>
#include <math.h>

#define B_      8
#define N_      512
#define NFEAT   32
#define NHID    128
#define NHEADS  4
#define M_      (B_ * N_)          // 4096 rows

#define ACT_NONE  0
#define ACT_LRELU 1
#define ACT_ELU   2

// ---------------- scratch (device globals; no runtime allocation) ----------
__device__ float g_bufA[M_ * NHID];            // 2 MB   "h"
__device__ float g_bufB[M_ * 2 * NHID];        // 4 MB   wide tmp
__device__ float g_bufC[M_ * NHID];            // 2 MB   res / gemm out
__device__ float g_Wh[NHEADS * M_ * NHID];     // 8 MB   per-head Wh
__device__ float g_cat[M_ * NHEADS * NHID];    // 8 MB   concat(hp)
__device__ float g_hsave[M_ * NHID];           // 2 MB   forward-branch output
__device__ float g_s1[NHEADS * M_];
__device__ float g_s2[NHEADS * M_];
__device__ int   g_adjT[B_ * N_ * N_];         // 8 MB

// ---------------- helpers ---------------------------------------------------
__device__ __forceinline__ float apply_act(float v, int act) {
    if (act == ACT_LRELU) return v >= 0.f ? v : 0.01f * v;
    if (act == ACT_ELU)   return v > 0.f ? v : expm1f(v);
    return v;
}

// ---------------- adj transpose ---------------------------------------------
__global__ void transpose512(const int* __restrict__ in, int* __restrict__ out) {
    __shared__ int tile[32][33];
    int b = blockIdx.z;
    int x0 = blockIdx.x * 32, y0 = blockIdx.y * 32;
    const int* ib = in + (size_t)b * N_ * N_;
    int* ob = out + (size_t)b * N_ * N_;
    for (int r = threadIdx.y; r < 32; r += 8)
        tile[r][threadIdx.x] = ib[(size_t)(y0 + r) * N_ + x0 + threadIdx.x];
    __syncthreads();
    for (int r = threadIdx.y; r < 32; r += 8)
        ob[(size_t)(x0 + r) * N_ + y0 + threadIdx.x] = tile[threadIdx.x][r];
}

// ---------------- GEMM: C[z] = act(A @ W[z] + bias), M fixed 4096 -----------
// 64x64 tile, BK=16, 256 threads, 4x4 microtile.
__global__ __launch_bounds__(256)
void gemm64(const float* __restrict__ A, const float* __restrict__ W,
            const float* __restrict__ bias, float* __restrict__ C,
            int K, int Nc, int act, size_t wz, size_t cz) {
    int z = blockIdx.z;
    W += (size_t)z * wz;
    C += (size_t)z * cz;

    __shared__ float As[16][65];
    __shared__ float Bs[16][64];

    int t = threadIdx.x;
    int tx = t & 15, ty = t >> 4;
    int row0 = blockIdx.y * 64, col0 = blockIdx.x * 64;

    float acc[4][4];
#pragma unroll
    for (int i = 0; i < 4; i++)
#pragma unroll
        for (int j = 0; j < 4; j++) acc[i][j] = 0.f;

    for (int k0 = 0; k0 < K; k0 += 16) {
#pragma unroll
        for (int l = 0; l < 4; l++) {
            int idx = t + l * 256;
            int r = idx >> 4, k = idx & 15;
            As[k][r] = A[(size_t)(row0 + r) * K + k0 + k];
        }
#pragma unroll
        for (int l = 0; l < 4; l++) {
            int idx = t + l * 256;
            int c = idx & 63, k = idx >> 6;
            Bs[k][c] = W[(size_t)(k0 + k) * Nc + col0 + c];
        }
        __syncthreads();
#pragma unroll
        for (int k = 0; k < 16; k++) {
            float av[4], bv[4];
#pragma unroll
            for (int i = 0; i < 4; i++) av[i] = As[k][ty + 16 * i];
#pragma unroll
            for (int j = 0; j < 4; j++) bv[j] = Bs[k][tx + 16 * j];
#pragma unroll
            for (int i = 0; i < 4; i++)
#pragma unroll
                for (int j = 0; j < 4; j++) acc[i][j] += av[i] * bv[j];
        }
        __syncthreads();
    }

#pragma unroll
    for (int i = 0; i < 4; i++) {
        int r = row0 + ty + 16 * i;
#pragma unroll
        for (int j = 0; j < 4; j++) {
            int c = col0 + tx + 16 * j;
            float v = acc[i][j] + (bias ? bias[c] : 0.f);
            C[(size_t)r * Nc + c] = apply_act(v, act);
        }
    }
}

// ---------------- LayerNorm(a + b) over last dim 128 ------------------------
__global__ void ln_add(const float* __restrict__ a, const float* __restrict__ b,
                       float* __restrict__ out, float* __restrict__ out2) {
    int row = blockIdx.x;
    int t = threadIdx.x;  // 128
    float v = a[(size_t)row * NHID + t];
    if (b) v += b[(size_t)row * NHID + t];

    __shared__ float ws[4], ws2[4];
    float s = v;
#pragma unroll
    for (int o = 16; o; o >>= 1) s += __shfl_xor_sync(0xffffffffu, s, o);
    if ((t & 31) == 0) ws[t >> 5] = s;
    __syncthreads();
    float mean = (ws[0] + ws[1] + ws[2] + ws[3]) * (1.f / NHID);
    float d = v - mean;
    float q = d * d;
#pragma unroll
    for (int o = 16; o; o >>= 1) q += __shfl_xor_sync(0xffffffffu, q, o);
    if ((t & 31) == 0) ws2[t >> 5] = q;
    __syncthreads();
    float var = (ws2[0] + ws2[1] + ws2[2] + ws2[3]) * (1.f / NHID);
    float y = d * rsqrtf(var + 1e-5f);
    out[(size_t)row * NHID + t] = y;
    if (out2) out2[(size_t)row * NHID + t] = y;
}

// ---------------- s1/s2 = Wh . a[:128], Wh . a[128:] -------------------------
__global__ void s1s2_kernel(const float* __restrict__ Wh, const float* __restrict__ avec,
                            float* __restrict__ s1, float* __restrict__ s2, int aStride) {
    int z = blockIdx.y;
    int row = blockIdx.x * 8 + (threadIdx.x >> 5);
    int lane = threadIdx.x & 31;
    const float* w = Wh + ((size_t)z * M_ + row) * NHID;
    const float* a = avec + (size_t)z * aStride;
    float4 wv = ((const float4*)w)[lane];
    float4 a1 = ((const float4*)a)[lane];
    float4 a2 = ((const float4*)(a + NHID))[lane];
    float d1 = wv.x * a1.x + wv.y * a1.y + wv.z * a1.z + wv.w * a1.w;
    float d2 = wv.x * a2.x + wv.y * a2.y + wv.z * a2.z + wv.w * a2.w;
#pragma unroll
    for (int o = 16; o; o >>= 1) {
        d1 += __shfl_xor_sync(0xffffffffu, d1, o);
        d2 += __shfl_xor_sync(0xffffffffu, d2, o);
    }
    if (lane == 0) {
        s1[(size_t)z * M_ + row] = d1;
        s2[(size_t)z * M_ + row] = d2;
    }
}

// ---------------- fused GAT attention ---------------------------------------
// Block handles (z=head, b=batch, 32 query rows). Rank-1 scores
// e[i,j] = lrelu(s1[i]*s2[j]) masked by adj>0, softmax over j, then P @ Wh.
__global__ __launch_bounds__(256)
void gat_attn(const float* __restrict__ Wh, const float* __restrict__ s1g,
              const float* __restrict__ s2g, const int* __restrict__ adj,
              float* __restrict__ out, int outRowStride, int act) {
    int z = blockIdx.z, b = blockIdx.y;
    int i0 = blockIdx.x * 32;
    int t = threadIdx.x;
    int w = t >> 5, lane = t & 31;

    __shared__ float s2sh[N_];
    __shared__ float s1sh[32];
    __shared__ float msh[32], invsh[32];
    __shared__ float whs[32][128];
    __shared__ float wsh[32][32];

    const size_t zrow = (size_t)z * M_;
    const float* WhB = Wh + (zrow + (size_t)b * N_) * NHID;
    const int* adjB = adj + (size_t)b * N_ * N_;

    s2sh[t] = s2g[zrow + (size_t)b * N_ + t];
    s2sh[t + 256] = s2g[zrow + (size_t)b * N_ + t + 256];
    if (t < 32) s1sh[t] = s1g[zrow + (size_t)b * N_ + i0 + t];
    __syncthreads();

    // Phase A: softmax stats (max + denom) per query row
    for (int q = 0; q < 4; q++) {
        int il = w * 4 + q;
        int ig = i0 + il;
        float s1v = s1sh[il];
        const int* arow = adjB + (size_t)ig * N_;
        float m = -1e30f;
        for (int j = lane; j < N_; j += 32) {
            if (arow[j] > 0) {
                float x = s1v * s2sh[j];
                float e = x >= 0.f ? x : 0.01f * x;
                m = fmaxf(m, e);
            }
        }
#pragma unroll
        for (int o = 16; o; o >>= 1) m = fmaxf(m, __shfl_xor_sync(0xffffffffu, m, o));
        float sden = 0.f;
        for (int j = lane; j < N_; j += 32) {
            if (arow[j] > 0) {
                float x = s1v * s2sh[j];
                float e = x >= 0.f ? x : 0.01f * x;
                sden += __expf(e - m);
            }
        }
#pragma unroll
        for (int o = 16; o; o >>= 1) sden += __shfl_xor_sync(0xffffffffu, sden, o);
        if (lane == 0) {
            msh[il] = m;
            invsh[il] = sden > 0.f ? 1.f / sden : 0.f;
        }
    }
    __syncthreads();

    // Phase B: hp = P @ Wh, streaming 32-row j tiles through smem
    float acc[4][4];
#pragma unroll
    for (int q = 0; q < 4; q++)
#pragma unroll
        for (int c = 0; c < 4; c++) acc[q][c] = 0.f;

    for (int j0 = 0; j0 < N_; j0 += 32) {
        __syncthreads();
#pragma unroll
        for (int l = 0; l < 4; l++) {
            int idx = t + l * 256;
            int jj = idx >> 5, c4 = idx & 31;
            ((float4*)&whs[jj][0])[c4] =
                ((const float4*)(WhB + (size_t)(j0 + jj) * NHID))[c4];
        }
#pragma unroll
        for (int l = 0; l < 4; l++) {
            int idx = t + l * 256;
            int ii = idx >> 5, jj = idx & 31;
            int jg = j0 + jj;
            int ig = i0 + ii;
            float wv = 0.f;
            if (adjB[(size_t)ig * N_ + jg] > 0) {
                float x = s1sh[ii] * s2sh[jg];
                float e = x >= 0.f ? x : 0.01f * x;
                wv = __expf(e - msh[ii]) * invsh[ii];
            }
            wsh[ii][jj] = wv;
        }
        __syncthreads();
#pragma unroll 4
        for (int jj = 0; jj < 32; jj++) {
            float4 v = *(const float4*)&whs[jj][lane * 4];
#pragma unroll
            for (int q = 0; q < 4; q++) {
                float wq = wsh[w * 4 + q][jj];
                acc[q][0] += wq * v.x;
                acc[q][1] += wq * v.y;
                acc[q][2] += wq * v.z;
                acc[q][3] += wq * v.w;
            }
        }
    }

    // epilogue
#pragma unroll
    for (int q = 0; q < 4; q++) {
        int ig = i0 + w * 4 + q;
        float4 r;
        r.x = apply_act(acc[q][0], act);
        r.y = apply_act(acc[q][1], act);
        r.z = apply_act(acc[q][2], act);
        r.w = apply_act(acc[q][3], act);
        size_t off = (size_t)(b * N_ + ig) * outRowStride + z * NHID + lane * 4;
        *(float4*)&out[off] = r;
    }
}

// ---------------- copy ------------------------------------------------------
__global__ void copyf(const float* __restrict__ a, float* __restrict__ o1,
                      float* __restrict__ o2, int n) {
    int i = blockIdx.x * 256 + threadIdx.x;
    if (i < n) {
        float v = a[i];
        o1[i] = v;
        if (o2) o2[i] = v;
    }
}

// ---------------- final mean + projection -----------------------------------
__global__ void finalize(const float* __restrict__ h, const float* __restrict__ ht,
                         const float* __restrict__ pW, const float* __restrict__ pb,
                         float* __restrict__ out) {
    int b = blockIdx.x;
    int t = threadIdx.x;  // 256
    const float* src = (t < NHID) ? h : ht;
    int c = t & (NHID - 1);
    float s = 0.f;
    for (int n = 0; n < N_; n++)
        s += src[((size_t)b * N_ + n) * NHID + c];
    s *= (1.f / N_);
    float contrib = s * pW[t];
    __shared__ float red[256];
    red[t] = contrib;
    __syncthreads();
    for (int st = 128; st; st >>= 1) {
        if (t < st) red[t] += red[t + st];
        __syncthreads();
    }
    if (t == 0) out[b] = red[0] + pb[0];
}

// ---------------- host orchestration ----------------------------------------
extern "C" void kernel_launch(void* const* d_in, const int* in_sizes, int n_in,
                              void* d_out, int out_size) {
    (void)in_sizes; (void)n_in; (void)out_size;
    const float* x     = (const float*)d_in[0];
    const int*   adj   = (const int*)d_in[1];
    // d_in[2] = layer_id (unused by reference)
    const float* f1w1  = (const float*)d_in[3];
    const float* f1b1  = (const float*)d_in[4];
    const float* f1w2  = (const float*)d_in[5];
    const float* f1b2  = (const float*)d_in[6];
    const float* f2w1  = (const float*)d_in[7];
    const float* f2b1  = (const float*)d_in[8];
    const float* f2w2  = (const float*)d_in[9];
    const float* f2b2  = (const float*)d_in[10];
    const float* f3w1  = (const float*)d_in[11];
    const float* f3b1  = (const float*)d_in[12];
    const float* f3w2  = (const float*)d_in[13];
    const float* f3b2  = (const float*)d_in[14];
    const float* att_W = (const float*)d_in[15];
    const float* att_a = (const float*)d_in[16];
    const float* resh_W= (const float*)d_in[17];
    const float* resh_b= (const float*)d_in[18];
    const float* out_W = (const float*)d_in[19];
    const float* out_a = (const float*)d_in[20];
    const float* proj_W= (const float*)d_in[21];
    const float* proj_b= (const float*)d_in[22];
    float* out = (float*)d_out;

    float *bufA, *bufB, *bufC, *Wh, *cat, *hsave, *s1, *s2;
    int* adjT;
    cudaGetSymbolAddress((void**)&bufA, g_bufA);
    cudaGetSymbolAddress((void**)&bufB, g_bufB);
    cudaGetSymbolAddress((void**)&bufC, g_bufC);
    cudaGetSymbolAddress((void**)&Wh, g_Wh);
    cudaGetSymbolAddress((void**)&cat, g_cat);
    cudaGetSymbolAddress((void**)&hsave, g_hsave);
    cudaGetSymbolAddress((void**)&s1, g_s1);
    cudaGetSymbolAddress((void**)&s2, g_s2);
    cudaGetSymbolAddress((void**)&adjT, g_adjT);

    // adj transpose (backward-branch mask)
    transpose512<<<dim3(16, 16, 8), dim3(32, 8)>>>(adj, adjT);

    // ---- feature extractor (_fel) ----
    gemm64<<<dim3(2, 64, 1), 256>>>(x,    f1w1, f1b1, bufA, NFEAT, NHID,     ACT_LRELU, 0, 0);
    gemm64<<<dim3(2, 64, 1), 256>>>(bufA, f1w2, f1b2, bufC, NHID,  NHID,     ACT_LRELU, 0, 0);
    gemm64<<<dim3(4, 64, 1), 256>>>(bufC, f2w1, f2b1, bufB, NHID,  2 * NHID, ACT_LRELU, 0, 0);
    gemm64<<<dim3(2, 64, 1), 256>>>(bufB, f2w2, f2b2, bufA, 2 * NHID, NHID,  ACT_LRELU, 0, 0);
    ln_add<<<M_, NHID>>>(bufA, bufC, bufA, bufC);                 // x = LN(h+res); res copy
    gemm64<<<dim3(4, 64, 1), 256>>>(bufC, f3w1, f3b1, bufB, NHID,  2 * NHID, ACT_LRELU, 0, 0);
    gemm64<<<dim3(2, 64, 1), 256>>>(bufB, f3w2, f3b2, bufA, 2 * NHID, NHID,  ACT_NONE,  0, 0);
    ln_add<<<M_, NHID>>>(bufA, bufC, bufA, nullptr);              // h in bufA

    // ---- helper lambdas ----
    auto attn_block = [&](int i, const int* mask) {
        const float* Wptr = att_W + (size_t)i * NHEADS * NHID * NHID;
        const float* aptr = att_a + (size_t)i * NHEADS * 2 * NHID;
        const float* rW   = resh_W + (size_t)i * (NHEADS * NHID) * NHID;
        const float* rb   = resh_b + (size_t)i * NHID;
        gemm64<<<dim3(2, 64, NHEADS), 256>>>(bufA, Wptr, nullptr, Wh, NHID, NHID,
                                             ACT_NONE, (size_t)NHID * NHID, (size_t)M_ * NHID);
        s1s2_kernel<<<dim3(M_ / 8, NHEADS), 256>>>(Wh, aptr, s1, s2, 2 * NHID);
        gat_attn<<<dim3(N_ / 32, B_, NHEADS), 256>>>(Wh, s1, s2, mask, cat,
                                                     NHEADS * NHID, ACT_ELU);
        gemm64<<<dim3(2, 64, 1), 256>>>(cat, rW, rb, bufC, NHEADS * NHID, NHID, ACT_NONE, 0, 0);
        ln_add<<<M_, NHID>>>(bufC, bufA, bufA, nullptr);
    };
    auto out_gat = [&](int sel, const int* mask, float* dst) {
        const float* Wptr = out_W + (size_t)sel * NHID * NHID;
        const float* aptr = out_a + (size_t)sel * 2 * NHID;
        gemm64<<<dim3(2, 64, 1), 256>>>(bufA, Wptr, nullptr, Wh, NHID, NHID, ACT_NONE, 0, 0);
        s1s2_kernel<<<dim3(M_ / 8, 1), 256>>>(Wh, aptr, s1, s2, 0);
        gat_attn<<<dim3(N_ / 32, B_, 1), 256>>>(Wh, s1, s2, mask, dst, NHID, ACT_LRELU);
    };

    // ---- forward branch ----
    attn_block(0, adj);
    attn_block(1, adj);
    attn_block(2, adj);
    out_gat(0, adj, bufC);                         // bufC = h (forward output)
    copyf<<<(M_ * NHID + 255) / 256, 256>>>(bufC, hsave, bufA, M_ * NHID);

    // ---- backward branch (transposed mask) ----
    attn_block(3, adjT);
    attn_block(4, adjT);
    attn_block(5, adjT);
    out_gat(1, adjT, bufC);                        // bufC = ht

    // ---- mean over nodes + projection ----
    finalize<<<B_, 256>>>(hsave, bufC, proj_W, proj_b, out);
}

// round 16
// speedup vs baseline: 1.0018x; 1.0018x over previous
#include <cuda_runtime.h>
#include <math.h>

#define B_      8
#define N_      512
#define NFEAT   32
#define NHID    128
#define NHEADS  4
#define M_      (B_ * N_)          // 4096 rows

#define ACT_NONE  0
#define ACT_LRELU 1
#define ACT_ELU   2

// ---------------- scratch (device globals; no runtime allocation) ----------
__device__ float g_bufA[M_ * NHID];            // 2 MB   "h"
__device__ float g_bufB[M_ * 2 * NHID];        // 4 MB   wide tmp
__device__ float g_bufC[M_ * NHID];            // 2 MB   res / gemm out
__device__ float g_Wh[NHEADS * M_ * NHID];     // 8 MB   per-head Wh
__device__ float g_cat[M_ * NHEADS * NHID];    // 8 MB   concat(hp)
__device__ float g_hsave[M_ * NHID];           // 2 MB   forward-branch output
__device__ float g_s1[NHEADS * M_];
__device__ float g_s2[NHEADS * M_];
__device__ int   g_adjT[B_ * N_ * N_];         // 8 MB

// ---------------- helpers ---------------------------------------------------
__device__ __forceinline__ float apply_act(float v, int act) {
    if (act == ACT_LRELU) return v >= 0.f ? v : 0.01f * v;
    if (act == ACT_ELU)   return v > 0.f ? v : expm1f(v);
    return v;
}

// ---------------- adj transpose ---------------------------------------------
__global__ void transpose512(const int* __restrict__ in, int* __restrict__ out) {
    __shared__ int tile[32][33];
    int b = blockIdx.z;
    int x0 = blockIdx.x * 32, y0 = blockIdx.y * 32;
    const int* ib = in + (size_t)b * N_ * N_;
    int* ob = out + (size_t)b * N_ * N_;
    for (int r = threadIdx.y; r < 32; r += 8)
        tile[r][threadIdx.x] = ib[(size_t)(y0 + r) * N_ + x0 + threadIdx.x];
    __syncthreads();
    for (int r = threadIdx.y; r < 32; r += 8)
        ob[(size_t)(x0 + r) * N_ + y0 + threadIdx.x] = tile[threadIdx.x][r];
}

// ---------------- GEMM: C[z] = act(A @ W[z] + bias), M fixed 4096 -----------
// 64x64 tile, BK=16, 256 threads, 4x4 microtile.
__global__ __launch_bounds__(256)
void gemm64(const float* __restrict__ A, const float* __restrict__ W,
            const float* __restrict__ bias, float* __restrict__ C,
            int K, int Nc, int act, size_t wz, size_t cz) {
    int z = blockIdx.z;
    W += (size_t)z * wz;
    C += (size_t)z * cz;

    __shared__ float As[16][65];
    __shared__ float Bs[16][64];

    int t = threadIdx.x;
    int tx = t & 15, ty = t >> 4;
    int row0 = blockIdx.y * 64, col0 = blockIdx.x * 64;

    float acc[4][4];
#pragma unroll
    for (int i = 0; i < 4; i++)
#pragma unroll
        for (int j = 0; j < 4; j++) acc[i][j] = 0.f;

    for (int k0 = 0; k0 < K; k0 += 16) {
#pragma unroll
        for (int l = 0; l < 4; l++) {
            int idx = t + l * 256;
            int r = idx >> 4, k = idx & 15;
            As[k][r] = A[(size_t)(row0 + r) * K + k0 + k];
        }
#pragma unroll
        for (int l = 0; l < 4; l++) {
            int idx = t + l * 256;
            int c = idx & 63, k = idx >> 6;
            Bs[k][c] = W[(size_t)(k0 + k) * Nc + col0 + c];
        }
        __syncthreads();
#pragma unroll
        for (int k = 0; k < 16; k++) {
            float av[4], bv[4];
#pragma unroll
            for (int i = 0; i < 4; i++) av[i] = As[k][ty + 16 * i];
#pragma unroll
            for (int j = 0; j < 4; j++) bv[j] = Bs[k][tx + 16 * j];
#pragma unroll
            for (int i = 0; i < 4; i++)
#pragma unroll
                for (int j = 0; j < 4; j++) acc[i][j] += av[i] * bv[j];
        }
        __syncthreads();
    }

#pragma unroll
    for (int i = 0; i < 4; i++) {
        int r = row0 + ty + 16 * i;
#pragma unroll
        for (int j = 0; j < 4; j++) {
            int c = col0 + tx + 16 * j;
            float v = acc[i][j] + (bias ? bias[c] : 0.f);
            C[(size_t)r * Nc + c] = apply_act(v, act);
        }
    }
}

// ---------------- LayerNorm(a + b) over last dim 128 ------------------------
__global__ void ln_add(const float* __restrict__ a, const float* __restrict__ b,
                       float* __restrict__ out, float* __restrict__ out2) {
    int row = blockIdx.x;
    int t = threadIdx.x;  // 128
    float v = a[(size_t)row * NHID + t];
    if (b) v += b[(size_t)row * NHID + t];

    __shared__ float ws[4], ws2[4];
    float s = v;
#pragma unroll
    for (int o = 16; o; o >>= 1) s += __shfl_xor_sync(0xffffffffu, s, o);
    if ((t & 31) == 0) ws[t >> 5] = s;
    __syncthreads();
    float mean = (ws[0] + ws[1] + ws[2] + ws[3]) * (1.f / NHID);
    float d = v - mean;
    float q = d * d;
#pragma unroll
    for (int o = 16; o; o >>= 1) q += __shfl_xor_sync(0xffffffffu, q, o);
    if ((t & 31) == 0) ws2[t >> 5] = q;
    __syncthreads();
    float var = (ws2[0] + ws2[1] + ws2[2] + ws2[3]) * (1.f / NHID);
    float y = d * rsqrtf(var + 1e-5f);
    out[(size_t)row * NHID + t] = y;
    if (out2) out2[(size_t)row * NHID + t] = y;
}

// ---------------- s1/s2 = Wh . a[:128], Wh . a[128:] -------------------------
__global__ void s1s2_kernel(const float* __restrict__ Wh, const float* __restrict__ avec,
                            float* __restrict__ s1, float* __restrict__ s2, int aStride) {
    int z = blockIdx.y;
    int row = blockIdx.x * 8 + (threadIdx.x >> 5);
    int lane = threadIdx.x & 31;
    const float* w = Wh + ((size_t)z * M_ + row) * NHID;
    const float* a = avec + (size_t)z * aStride;
    float4 wv = ((const float4*)w)[lane];
    float4 a1 = ((const float4*)a)[lane];
    float4 a2 = ((const float4*)(a + NHID))[lane];
    float d1 = wv.x * a1.x + wv.y * a1.y + wv.z * a1.z + wv.w * a1.w;
    float d2 = wv.x * a2.x + wv.y * a2.y + wv.z * a2.z + wv.w * a2.w;
#pragma unroll
    for (int o = 16; o; o >>= 1) {
        d1 += __shfl_xor_sync(0xffffffffu, d1, o);
        d2 += __shfl_xor_sync(0xffffffffu, d2, o);
    }
    if (lane == 0) {
        s1[(size_t)z * M_ + row] = d1;
        s2[(size_t)z * M_ + row] = d2;
    }
}

// ---------------- fused GAT attention ---------------------------------------
// Block handles (z=head, b=batch, 32 query rows). Rank-1 scores
// e[i,j] = lrelu(s1[i]*s2[j]) masked by adj>0, softmax over j, then P @ Wh.
__global__ __launch_bounds__(256)
void gat_attn(const float* __restrict__ Wh, const float* __restrict__ s1g,
              const float* __restrict__ s2g, const int* __restrict__ adj,
              float* __restrict__ out, int outRowStride, int act) {
    int z = blockIdx.z, b = blockIdx.y;
    int i0 = blockIdx.x * 32;
    int t = threadIdx.x;
    int w = t >> 5, lane = t & 31;

    __shared__ float s2sh[N_];
    __shared__ float s1sh[32];
    __shared__ float msh[32], invsh[32];
    __shared__ float whs[32][128];
    __shared__ float wsh[32][32];

    const size_t zrow = (size_t)z * M_;
    const float* WhB = Wh + (zrow + (size_t)b * N_) * NHID;
    const int* adjB = adj + (size_t)b * N_ * N_;

    s2sh[t] = s2g[zrow + (size_t)b * N_ + t];
    s2sh[t + 256] = s2g[zrow + (size_t)b * N_ + t + 256];
    if (t < 32) s1sh[t] = s1g[zrow + (size_t)b * N_ + i0 + t];
    __syncthreads();

    // Phase A: softmax stats (max + denom) per query row
    for (int q = 0; q < 4; q++) {
        int il = w * 4 + q;
        int ig = i0 + il;
        float s1v = s1sh[il];
        const int* arow = adjB + (size_t)ig * N_;
        float m = -1e30f;
        for (int j = lane; j < N_; j += 32) {
            if (arow[j] > 0) {
                float x = s1v * s2sh[j];
                float e = x >= 0.f ? x : 0.01f * x;
                m = fmaxf(m, e);
            }
        }
#pragma unroll
        for (int o = 16; o; o >>= 1) m = fmaxf(m, __shfl_xor_sync(0xffffffffu, m, o));
        float sden = 0.f;
        for (int j = lane; j < N_; j += 32) {
            if (arow[j] > 0) {
                float x = s1v * s2sh[j];
                float e = x >= 0.f ? x : 0.01f * x;
                sden += __expf(e - m);
            }
        }
#pragma unroll
        for (int o = 16; o; o >>= 1) sden += __shfl_xor_sync(0xffffffffu, sden, o);
        if (lane == 0) {
            msh[il] = m;
            invsh[il] = sden > 0.f ? 1.f / sden : 0.f;
        }
    }
    __syncthreads();

    // Phase B: hp = P @ Wh, streaming 32-row j tiles through smem
    float acc[4][4];
#pragma unroll
    for (int q = 0; q < 4; q++)
#pragma unroll
        for (int c = 0; c < 4; c++) acc[q][c] = 0.f;

    for (int j0 = 0; j0 < N_; j0 += 32) {
        __syncthreads();
#pragma unroll
        for (int l = 0; l < 4; l++) {
            int idx = t + l * 256;
            int jj = idx >> 5, c4 = idx & 31;
            ((float4*)&whs[jj][0])[c4] =
                ((const float4*)(WhB + (size_t)(j0 + jj) * NHID))[c4];
        }
#pragma unroll
        for (int l = 0; l < 4; l++) {
            int idx = t + l * 256;
            int ii = idx >> 5, jj = idx & 31;
            int jg = j0 + jj;
            int ig = i0 + ii;
            float wv = 0.f;
            if (adjB[(size_t)ig * N_ + jg] > 0) {
                float x = s1sh[ii] * s2sh[jg];
                float e = x >= 0.f ? x : 0.01f * x;
                wv = __expf(e - msh[ii]) * invsh[ii];
            }
            wsh[ii][jj] = wv;
        }
        __syncthreads();
#pragma unroll 4
        for (int jj = 0; jj < 32; jj++) {
            float4 v = *(const float4*)&whs[jj][lane * 4];
#pragma unroll
            for (int q = 0; q < 4; q++) {
                float wq = wsh[w * 4 + q][jj];
                acc[q][0] += wq * v.x;
                acc[q][1] += wq * v.y;
                acc[q][2] += wq * v.z;
                acc[q][3] += wq * v.w;
            }
        }
    }

    // epilogue
#pragma unroll
    for (int q = 0; q < 4; q++) {
        int ig = i0 + w * 4 + q;
        float4 r;
        r.x = apply_act(acc[q][0], act);
        r.y = apply_act(acc[q][1], act);
        r.z = apply_act(acc[q][2], act);
        r.w = apply_act(acc[q][3], act);
        size_t off = (size_t)(b * N_ + ig) * outRowStride + z * NHID + lane * 4;
        *(float4*)&out[off] = r;
    }
}

// ---------------- copy ------------------------------------------------------
__global__ void copyf(const float* __restrict__ a, float* __restrict__ o1,
                      float* __restrict__ o2, int n) {
    int i = blockIdx.x * 256 + threadIdx.x;
    if (i < n) {
        float v = a[i];
        o1[i] = v;
        if (o2) o2[i] = v;
    }
}

// ---------------- final mean + projection -----------------------------------
__global__ void finalize(const float* __restrict__ h, const float* __restrict__ ht,
                         const float* __restrict__ pW, const float* __restrict__ pb,
                         float* __restrict__ out) {
    int b = blockIdx.x;
    int t = threadIdx.x;  // 256
    const float* src = (t < NHID) ? h : ht;
    int c = t & (NHID - 1);
    float s = 0.f;
    for (int n = 0; n < N_; n++)
        s += src[((size_t)b * N_ + n) * NHID + c];
    s *= (1.f / N_);
    float contrib = s * pW[t];
    __shared__ float red[256];
    red[t] = contrib;
    __syncthreads();
    for (int st = 128; st; st >>= 1) {
        if (t < st) red[t] += red[t + st];
        __syncthreads();
    }
    if (t == 0) out[b] = red[0] + pb[0];
}

// ---------------- host orchestration ----------------------------------------
extern "C" void kernel_launch(void* const* d_in, const int* in_sizes, int n_in,
                              void* d_out, int out_size) {
    (void)in_sizes; (void)n_in; (void)out_size;
    const float* x     = (const float*)d_in[0];
    const int*   adj   = (const int*)d_in[1];
    // d_in[2] = layer_id (unused by reference)
    const float* f1w1  = (const float*)d_in[3];
    const float* f1b1  = (const float*)d_in[4];
    const float* f1w2  = (const float*)d_in[5];
    const float* f1b2  = (const float*)d_in[6];
    const float* f2w1  = (const float*)d_in[7];
    const float* f2b1  = (const float*)d_in[8];
    const float* f2w2  = (const float*)d_in[9];
    const float* f2b2  = (const float*)d_in[10];
    const float* f3w1  = (const float*)d_in[11];
    const float* f3b1  = (const float*)d_in[12];
    const float* f3w2  = (const float*)d_in[13];
    const float* f3b2  = (const float*)d_in[14];
    const float* att_W = (const float*)d_in[15];
    const float* att_a = (const float*)d_in[16];
    const float* resh_W= (const float*)d_in[17];
    const float* resh_b= (const float*)d_in[18];
    const float* out_W = (const float*)d_in[19];
    const float* out_a = (const float*)d_in[20];
    const float* proj_W= (const float*)d_in[21];
    const float* proj_b= (const float*)d_in[22];
    float* out = (float*)d_out;

    float *bufA, *bufB, *bufC, *Wh, *cat, *hsave, *s1, *s2;
    int* adjT;
    cudaGetSymbolAddress((void**)&bufA, g_bufA);
    cudaGetSymbolAddress((void**)&bufB, g_bufB);
    cudaGetSymbolAddress((void**)&bufC, g_bufC);
    cudaGetSymbolAddress((void**)&Wh, g_Wh);
    cudaGetSymbolAddress((void**)&cat, g_cat);
    cudaGetSymbolAddress((void**)&hsave, g_hsave);
    cudaGetSymbolAddress((void**)&s1, g_s1);
    cudaGetSymbolAddress((void**)&s2, g_s2);
    cudaGetSymbolAddress((void**)&adjT, g_adjT);

    // adj transpose (backward-branch mask)
    transpose512<<<dim3(16, 16, 8), dim3(32, 8)>>>(adj, adjT);

    // ---- feature extractor (_fel) ----
    gemm64<<<dim3(2, 64, 1), 256>>>(x,    f1w1, f1b1, bufA, NFEAT, NHID,     ACT_LRELU, 0, 0);
    gemm64<<<dim3(2, 64, 1), 256>>>(bufA, f1w2, f1b2, bufC, NHID,  NHID,     ACT_LRELU, 0, 0);
    gemm64<<<dim3(4, 64, 1), 256>>>(bufC, f2w1, f2b1, bufB, NHID,  2 * NHID, ACT_LRELU, 0, 0);
    gemm64<<<dim3(2, 64, 1), 256>>>(bufB, f2w2, f2b2, bufA, 2 * NHID, NHID,  ACT_LRELU, 0, 0);
    ln_add<<<M_, NHID>>>(bufA, bufC, bufA, bufC);                 // x = LN(h+res); res copy
    gemm64<<<dim3(4, 64, 1), 256>>>(bufC, f3w1, f3b1, bufB, NHID,  2 * NHID, ACT_LRELU, 0, 0);
    gemm64<<<dim3(2, 64, 1), 256>>>(bufB, f3w2, f3b2, bufA, 2 * NHID, NHID,  ACT_NONE,  0, 0);
    ln_add<<<M_, NHID>>>(bufA, bufC, bufA, nullptr);              // h in bufA

    // ---- helper lambdas ----
    auto attn_block = [&](int i, const int* mask) {
        const float* Wptr = att_W + (size_t)i * NHEADS * NHID * NHID;
        const float* aptr = att_a + (size_t)i * NHEADS * 2 * NHID;
        const float* rW   = resh_W + (size_t)i * (NHEADS * NHID) * NHID;
        const float* rb   = resh_b + (size_t)i * NHID;
        gemm64<<<dim3(2, 64, NHEADS), 256>>>(bufA, Wptr, nullptr, Wh, NHID, NHID,
                                             ACT_NONE, (size_t)NHID * NHID, (size_t)M_ * NHID);
        s1s2_kernel<<<dim3(M_ / 8, NHEADS), 256>>>(Wh, aptr, s1, s2, 2 * NHID);
        gat_attn<<<dim3(N_ / 32, B_, NHEADS), 256>>>(Wh, s1, s2, mask, cat,
                                                     NHEADS * NHID, ACT_ELU);
        gemm64<<<dim3(2, 64, 1), 256>>>(cat, rW, rb, bufC, NHEADS * NHID, NHID, ACT_NONE, 0, 0);
        ln_add<<<M_, NHID>>>(bufC, bufA, bufA, nullptr);
    };
    auto out_gat = [&](int sel, const int* mask, float* dst) {
        const float* Wptr = out_W + (size_t)sel * NHID * NHID;
        const float* aptr = out_a + (size_t)sel * 2 * NHID;
        gemm64<<<dim3(2, 64, 1), 256>>>(bufA, Wptr, nullptr, Wh, NHID, NHID, ACT_NONE, 0, 0);
        s1s2_kernel<<<dim3(M_ / 8, 1), 256>>>(Wh, aptr, s1, s2, 0);
        gat_attn<<<dim3(N_ / 32, B_, 1), 256>>>(Wh, s1, s2, mask, dst, NHID, ACT_LRELU);
    };

    // ---- forward branch ----
    attn_block(0, adj);
    attn_block(1, adj);
    attn_block(2, adj);
    out_gat(0, adj, bufC);                         // bufC = h (forward output)
    copyf<<<(M_ * NHID + 255) / 256, 256>>>(bufC, hsave, bufA, M_ * NHID);

    // ---- backward branch (transposed mask) ----
    attn_block(3, adjT);
    attn_block(4, adjT);
    attn_block(5, adjT);
    out_gat(1, adjT, bufC);                        // bufC = ht

    // ---- mean over nodes + projection ----
    finalize<<<B_, 256>>>(hsave, bufC, proj_W, proj_b, out);
}

// round 17
// speedup vs baseline: 1.0911x; 1.0891x over previous
#include <cuda_runtime.h>
#include <math.h>

#define B_      8
#define N_      512
#define NFEAT   32
#define NHID    128
#define NHEADS  4
#define M_      (B_ * N_)          // 4096 rows

#define ACT_NONE  0
#define ACT_LRELU 1
#define ACT_ELU   2

// ---------------- scratch (device globals; no runtime allocation) ----------
__device__ float g_bufA[M_ * NHID];            // 2 MB   "h"
__device__ float g_bufB[M_ * 2 * NHID];        // 4 MB   wide tmp
__device__ float g_bufC[M_ * NHID];            // 2 MB   res / gemm out
__device__ float g_Wh[NHEADS * M_ * NHID];     // 8 MB   per-head Wh
__device__ float g_cat[M_ * NHEADS * NHID];    // 8 MB   concat(hp)
__device__ float g_hsave[M_ * NHID];           // 2 MB   forward-branch output
__device__ float g_s1[NHEADS * M_];
__device__ float g_s2[NHEADS * M_];
__device__ int   g_adjT[B_ * N_ * N_];         // 8 MB
__device__ unsigned g_mask[M_ * 16];           // bit-packed adj  (row-major)
__device__ unsigned g_maskT[M_ * 16];          // bit-packed adjT

// ---------------- f32x2 packed-math helpers ---------------------------------
__device__ __forceinline__ unsigned long long pack2(float lo, float hi) {
    unsigned long long r;
    asm("mov.b64 %0, {%1, %2};" : "=l"(r) : "f"(lo), "f"(hi));
    return r;
}
__device__ __forceinline__ void unpack2(unsigned long long v, float& lo, float& hi) {
    asm("mov.b64 {%0, %1}, %2;" : "=f"(lo), "=f"(hi) : "l"(v));
}
__device__ __forceinline__ void ffma2(unsigned long long& d,
                                      unsigned long long a, unsigned long long b) {
    asm("fma.rn.f32x2 %0, %1, %2, %0;" : "+l"(d) : "l"(a), "l"(b));
}

__device__ __forceinline__ float apply_act(float v, int act) {
    if (act == ACT_LRELU) return v >= 0.f ? v : 0.01f * v;
    if (act == ACT_ELU)   return v > 0.f ? v : expm1f(v);
    return v;
}

// ---------------- adj transpose ---------------------------------------------
__global__ void transpose512(const int* __restrict__ in, int* __restrict__ out) {
    __shared__ int tile[32][33];
    int b = blockIdx.z;
    int x0 = blockIdx.x * 32, y0 = blockIdx.y * 32;
    const int* ib = in + (size_t)b * N_ * N_;
    int* ob = out + (size_t)b * N_ * N_;
    for (int r = threadIdx.y; r < 32; r += 8)
        tile[r][threadIdx.x] = ib[(size_t)(y0 + r) * N_ + x0 + threadIdx.x];
    __syncthreads();
    for (int r = threadIdx.y; r < 32; r += 8)
        ob[(size_t)(x0 + r) * N_ + y0 + threadIdx.x] = tile[threadIdx.x][r];
}

// ---------------- pack adjacency rows into 512-bit masks ---------------------
__global__ void pack_mask(const int* __restrict__ adj, unsigned* __restrict__ mask) {
    int row = blockIdx.x * 8 + (threadIdx.x >> 5);   // global row in [0, B*N)
    int lane = threadIdx.x & 31;
    const int* arow = adj + (size_t)row * N_;
#pragma unroll
    for (int w = 0; w < 16; w++) {
        unsigned m = __ballot_sync(0xffffffffu, arow[w * 32 + lane] > 0);
        if (lane == 0) mask[(size_t)row * 16 + w] = m;
    }
}

// ---------------- GEMM: C[z] = act(A @ W[z] + bias) -------------------------
// 64x64 tile, BK=16, 256 threads, double-buffered smem, f32x2 packed FMA.
__global__ __launch_bounds__(256)
void gemm64(const float* __restrict__ A, const float* __restrict__ W,
            const float* __restrict__ bias, float* __restrict__ C,
            int K, int Nc, int act, size_t wz, size_t cz) {
    int z = blockIdx.z;
    W += (size_t)z * wz;
    C += (size_t)z * cz;

    __shared__ float As[2][16][65];
    __shared__ float Bs[2][16][64];

    int t = threadIdx.x;
    int tx = t & 15, ty = t >> 4;
    int row0 = blockIdx.y * 64, col0 = blockIdx.x * 64;

    auto fill = [&](int s, int k0) {
        int r = t >> 2, kq = t & 3;
        float4 a4 = *(const float4*)(A + (size_t)(row0 + r) * K + k0 + kq * 4);
        As[s][kq * 4 + 0][r] = a4.x;
        As[s][kq * 4 + 1][r] = a4.y;
        As[s][kq * 4 + 2][r] = a4.z;
        As[s][kq * 4 + 3][r] = a4.w;
        int k = t >> 4, c4 = t & 15;
        float4 b4 = *(const float4*)(W + (size_t)(k0 + k) * Nc + col0 + c4 * 4);
        *(float4*)&Bs[s][k][c4 * 4] = b4;
    };

    unsigned long long acc[4][2];
#pragma unroll
    for (int i = 0; i < 4; i++)
#pragma unroll
        for (int j = 0; j < 2; j++) acc[i][j] = 0ull;

    fill(0, 0);
    __syncthreads();
    int nIt = K >> 4;
    for (int it = 0; it < nIt; it++) {
        int s = it & 1;
        if (it + 1 < nIt) fill(s ^ 1, (it + 1) << 4);
#pragma unroll
        for (int k = 0; k < 16; k++) {
            unsigned long long av2[4], bv[2];
#pragma unroll
            for (int i = 0; i < 4; i++) {
                float a = As[s][k][ty + 16 * i];
                av2[i] = pack2(a, a);
            }
#pragma unroll
            for (int j = 0; j < 2; j++)
                bv[j] = *(const unsigned long long*)&Bs[s][k][tx * 2 + 32 * j];
#pragma unroll
            for (int i = 0; i < 4; i++)
#pragma unroll
                for (int j = 0; j < 2; j++) ffma2(acc[i][j], av2[i], bv[j]);
        }
        __syncthreads();
    }

#pragma unroll
    for (int i = 0; i < 4; i++) {
        int r = row0 + ty + 16 * i;
#pragma unroll
        for (int j = 0; j < 2; j++) {
            int c = col0 + tx * 2 + 32 * j;
            float lo, hi;
            unpack2(acc[i][j], lo, hi);
            float bl = bias ? bias[c] : 0.f;
            float bh = bias ? bias[c + 1] : 0.f;
            float2 o;
            o.x = apply_act(lo + bl, act);
            o.y = apply_act(hi + bh, act);
            *(float2*)&C[(size_t)r * Nc + c] = o;
        }
    }
}

// ---------------- LayerNorm(a + b) over last dim 128 ------------------------
__global__ void ln_add(const float* __restrict__ a, const float* __restrict__ b,
                       float* __restrict__ out, float* __restrict__ out2) {
    int row = blockIdx.x;
    int t = threadIdx.x;  // 128
    float v = a[(size_t)row * NHID + t];
    if (b) v += b[(size_t)row * NHID + t];

    __shared__ float ws[4], ws2[4];
    float s = v;
#pragma unroll
    for (int o = 16; o; o >>= 1) s += __shfl_xor_sync(0xffffffffu, s, o);
    if ((t & 31) == 0) ws[t >> 5] = s;
    __syncthreads();
    float mean = (ws[0] + ws[1] + ws[2] + ws[3]) * (1.f / NHID);
    float d = v - mean;
    float q = d * d;
#pragma unroll
    for (int o = 16; o; o >>= 1) q += __shfl_xor_sync(0xffffffffu, q, o);
    if ((t & 31) == 0) ws2[t >> 5] = q;
    __syncthreads();
    float var = (ws2[0] + ws2[1] + ws2[2] + ws2[3]) * (1.f / NHID);
    float y = d * rsqrtf(var + 1e-5f);
    out[(size_t)row * NHID + t] = y;
    if (out2) out2[(size_t)row * NHID + t] = y;
}

// ---------------- s1/s2 = Wh . a[:128], Wh . a[128:] -------------------------
__global__ void s1s2_kernel(const float* __restrict__ Wh, const float* __restrict__ avec,
                            float* __restrict__ s1, float* __restrict__ s2, int aStride) {
    int z = blockIdx.y;
    int row = blockIdx.x * 8 + (threadIdx.x >> 5);
    int lane = threadIdx.x & 31;
    const float* w = Wh + ((size_t)z * M_ + row) * NHID;
    const float* a = avec + (size_t)z * aStride;
    float4 wv = ((const float4*)w)[lane];
    float4 a1 = ((const float4*)a)[lane];
    float4 a2 = ((const float4*)(a + NHID))[lane];
    float d1 = wv.x * a1.x + wv.y * a1.y + wv.z * a1.z + wv.w * a1.w;
    float d2 = wv.x * a2.x + wv.y * a2.y + wv.z * a2.z + wv.w * a2.w;
#pragma unroll
    for (int o = 16; o; o >>= 1) {
        d1 += __shfl_xor_sync(0xffffffffu, d1, o);
        d2 += __shfl_xor_sync(0xffffffffu, d2, o);
    }
    if (lane == 0) {
        s1[(size_t)z * M_ + row] = d1;
        s2[(size_t)z * M_ + row] = d2;
    }
}

// ---------------- fused GAT attention ---------------------------------------
// Block = (head z, batch b, 32 query rows). Rank-1 scores e=lrelu(s1[i]*s2[j]),
// bit-packed mask, online softmax stats, then P @ Wh double-buffered, f32x2.
__global__ __launch_bounds__(256)
void gat_attn(const float* __restrict__ Wh, const float* __restrict__ s1g,
              const float* __restrict__ s2g, const unsigned* __restrict__ mask,
              float* __restrict__ out, int outRowStride, int act) {
    int z = blockIdx.z, b = blockIdx.y;
    int i0 = blockIdx.x * 32;
    int t = threadIdx.x;
    int w = t >> 5, lane = t & 31;

    __shared__ float s2sh[N_];
    __shared__ float s1sh[32];
    __shared__ float msh[32], invsh[32];
    __shared__ unsigned msk[32][16];
    __shared__ float whs[2][32][128];
    __shared__ float wsh[2][32][33];

    size_t zb = (size_t)z * M_ + (size_t)b * N_;
    const float* WhB = Wh + zb * NHID;
    const unsigned* maskB = mask + (size_t)b * N_ * 16;

    s2sh[t] = s2g[zb + t];
    s2sh[t + 256] = s2g[zb + t + 256];
    if (t < 32) s1sh[t] = s1g[zb + i0 + t];
    msk[t >> 4][t & 15] = maskB[(size_t)(i0 + (t >> 4)) * 16 + (t & 15)];
    msk[16 + (t >> 4)][t & 15] = maskB[(size_t)(i0 + 16 + (t >> 4)) * 16 + (t & 15)];
    __syncthreads();

    // Phase A: softmax stats (max + denom) per query row, mask bits from smem
    for (int q = 0; q < 4; q++) {
        int il = w * 4 + q;
        float s1v = s1sh[il];
        float m = -1e30f;
#pragma unroll
        for (int wd = 0; wd < 16; wd++) {
            if ((msk[il][wd] >> lane) & 1u) {
                float x = s1v * s2sh[wd * 32 + lane];
                float e = x >= 0.f ? x : 0.01f * x;
                m = fmaxf(m, e);
            }
        }
#pragma unroll
        for (int o = 16; o; o >>= 1) m = fmaxf(m, __shfl_xor_sync(0xffffffffu, m, o));
        float sden = 0.f;
#pragma unroll
        for (int wd = 0; wd < 16; wd++) {
            if ((msk[il][wd] >> lane) & 1u) {
                float x = s1v * s2sh[wd * 32 + lane];
                float e = x >= 0.f ? x : 0.01f * x;
                sden += __expf(e - m);
            }
        }
#pragma unroll
        for (int o = 16; o; o >>= 1) sden += __shfl_xor_sync(0xffffffffu, sden, o);
        if (lane == 0) {
            msh[il] = m;
            invsh[il] = sden > 0.f ? 1.f / sden : 0.f;
        }
    }
    __syncthreads();

    // Phase B: hp = P @ Wh, double-buffered 32-row j tiles
    auto fill_tile = [&](int s, int j0) {
#pragma unroll
        for (int l = 0; l < 4; l++) {
            int idx = t + l * 256;
            int jj = idx >> 5, c4 = idx & 31;
            ((float4*)&whs[s][jj][0])[c4] =
                ((const float4*)(WhB + (size_t)(j0 + jj) * NHID))[c4];
        }
#pragma unroll
        for (int l = 0; l < 4; l++) {
            int ii = w + l * 8;
            unsigned word = msk[ii][j0 >> 5];
            float wv = 0.f;
            if ((word >> lane) & 1u) {
                float x = s1sh[ii] * s2sh[j0 + lane];
                float e = x >= 0.f ? x : 0.01f * x;
                wv = __expf(e - msh[ii]) * invsh[ii];
            }
            wsh[s][ii][lane] = wv;
        }
    };

    unsigned long long acc[4][2];
#pragma unroll
    for (int q = 0; q < 4; q++) {
        acc[q][0] = 0ull;
        acc[q][1] = 0ull;
    }

    fill_tile(0, 0);
    __syncthreads();
    for (int it = 0; it < 16; it++) {
        int s = it & 1;
        if (it + 1 < 16) fill_tile(s ^ 1, (it + 1) * 32);
#pragma unroll 4
        for (int jj = 0; jj < 32; jj++) {
            ulonglong2 v = *(const ulonglong2*)&whs[s][jj][lane * 4];
#pragma unroll
            for (int q = 0; q < 4; q++) {
                float wq = wsh[s][w * 4 + q][jj];
                unsigned long long w2 = pack2(wq, wq);
                ffma2(acc[q][0], w2, v.x);
                ffma2(acc[q][1], w2, v.y);
            }
        }
        __syncthreads();
    }

    // epilogue
#pragma unroll
    for (int q = 0; q < 4; q++) {
        int ig = i0 + w * 4 + q;
        float lo, hi;
        float4 r;
        unpack2(acc[q][0], lo, hi);
        r.x = apply_act(lo, act);
        r.y = apply_act(hi, act);
        unpack2(acc[q][1], lo, hi);
        r.z = apply_act(lo, act);
        r.w = apply_act(hi, act);
        size_t off = (size_t)(b * N_ + ig) * outRowStride + z * NHID + lane * 4;
        *(float4*)&out[off] = r;
    }
}

// ---------------- copy ------------------------------------------------------
__global__ void copyf(const float* __restrict__ a, float* __restrict__ o1,
                      float* __restrict__ o2, int n) {
    int i = blockIdx.x * 256 + threadIdx.x;
    if (i < n) {
        float v = a[i];
        o1[i] = v;
        if (o2) o2[i] = v;
    }
}

// ---------------- final mean + projection -----------------------------------
__global__ void finalize(const float* __restrict__ h, const float* __restrict__ ht,
                         const float* __restrict__ pW, const float* __restrict__ pb,
                         float* __restrict__ out) {
    int b = blockIdx.x;
    int t = threadIdx.x;  // 256
    const float* src = (t < NHID) ? h : ht;
    int c = t & (NHID - 1);
    float s = 0.f;
    for (int n = 0; n < N_; n++)
        s += src[((size_t)b * N_ + n) * NHID + c];
    s *= (1.f / N_);
    float contrib = s * pW[t];
    __shared__ float red[256];
    red[t] = contrib;
    __syncthreads();
    for (int st = 128; st; st >>= 1) {
        if (t < st) red[t] += red[t + st];
        __syncthreads();
    }
    if (t == 0) out[b] = red[0] + pb[0];
}

// ---------------- host orchestration ----------------------------------------
extern "C" void kernel_launch(void* const* d_in, const int* in_sizes, int n_in,
                              void* d_out, int out_size) {
    (void)in_sizes; (void)n_in; (void)out_size;
    const float* x     = (const float*)d_in[0];
    const int*   adj   = (const int*)d_in[1];
    // d_in[2] = layer_id (unused by reference)
    const float* f1w1  = (const float*)d_in[3];
    const float* f1b1  = (const float*)d_in[4];
    const float* f1w2  = (const float*)d_in[5];
    const float* f1b2  = (const float*)d_in[6];
    const float* f2w1  = (const float*)d_in[7];
    const float* f2b1  = (const float*)d_in[8];
    const float* f2w2  = (const float*)d_in[9];
    const float* f2b2  = (const float*)d_in[10];
    const float* f3w1  = (const float*)d_in[11];
    const float* f3b1  = (const float*)d_in[12];
    const float* f3w2  = (const float*)d_in[13];
    const float* f3b2  = (const float*)d_in[14];
    const float* att_W = (const float*)d_in[15];
    const float* att_a = (const float*)d_in[16];
    const float* resh_W= (const float*)d_in[17];
    const float* resh_b= (const float*)d_in[18];
    const float* out_W = (const float*)d_in[19];
    const float* out_a = (const float*)d_in[20];
    const float* proj_W= (const float*)d_in[21];
    const float* proj_b= (const float*)d_in[22];
    float* out = (float*)d_out;

    float *bufA, *bufB, *bufC, *Wh, *cat, *hsave, *s1, *s2;
    int* adjT;
    unsigned *maskp, *maskTp;
    cudaGetSymbolAddress((void**)&bufA, g_bufA);
    cudaGetSymbolAddress((void**)&bufB, g_bufB);
    cudaGetSymbolAddress((void**)&bufC, g_bufC);
    cudaGetSymbolAddress((void**)&Wh, g_Wh);
    cudaGetSymbolAddress((void**)&cat, g_cat);
    cudaGetSymbolAddress((void**)&hsave, g_hsave);
    cudaGetSymbolAddress((void**)&s1, g_s1);
    cudaGetSymbolAddress((void**)&s2, g_s2);
    cudaGetSymbolAddress((void**)&adjT, g_adjT);
    cudaGetSymbolAddress((void**)&maskp, g_mask);
    cudaGetSymbolAddress((void**)&maskTp, g_maskT);

    // masks: transpose + bit-pack both orientations
    transpose512<<<dim3(16, 16, 8), dim3(32, 8)>>>(adj, adjT);
    pack_mask<<<M_ / 8, 256>>>(adj, maskp);
    pack_mask<<<M_ / 8, 256>>>(adjT, maskTp);

    // ---- feature extractor (_fel) ----
    gemm64<<<dim3(2, 64, 1), 256>>>(x,    f1w1, f1b1, bufA, NFEAT, NHID,     ACT_LRELU, 0, 0);
    gemm64<<<dim3(2, 64, 1), 256>>>(bufA, f1w2, f1b2, bufC, NHID,  NHID,     ACT_LRELU, 0, 0);
    gemm64<<<dim3(4, 64, 1), 256>>>(bufC, f2w1, f2b1, bufB, NHID,  2 * NHID, ACT_LRELU, 0, 0);
    gemm64<<<dim3(2, 64, 1), 256>>>(bufB, f2w2, f2b2, bufA, 2 * NHID, NHID,  ACT_LRELU, 0, 0);
    ln_add<<<M_, NHID>>>(bufA, bufC, bufA, bufC);                 // x = LN(h+res); res copy
    gemm64<<<dim3(4, 64, 1), 256>>>(bufC, f3w1, f3b1, bufB, NHID,  2 * NHID, ACT_LRELU, 0, 0);
    gemm64<<<dim3(2, 64, 1), 256>>>(bufB, f3w2, f3b2, bufA, 2 * NHID, NHID,  ACT_NONE,  0, 0);
    ln_add<<<M_, NHID>>>(bufA, bufC, bufA, nullptr);              // h in bufA

    // ---- helper lambdas ----
    auto attn_block = [&](int i, const unsigned* m) {
        const float* Wptr = att_W + (size_t)i * NHEADS * NHID * NHID;
        const float* aptr = att_a + (size_t)i * NHEADS * 2 * NHID;
        const float* rW   = resh_W + (size_t)i * (NHEADS * NHID) * NHID;
        const float* rb   = resh_b + (size_t)i * NHID;
        gemm64<<<dim3(2, 64, NHEADS), 256>>>(bufA, Wptr, nullptr, Wh, NHID, NHID,
                                             ACT_NONE, (size_t)NHID * NHID, (size_t)M_ * NHID);
        s1s2_kernel<<<dim3(M_ / 8, NHEADS), 256>>>(Wh, aptr, s1, s2, 2 * NHID);
        gat_attn<<<dim3(N_ / 32, B_, NHEADS), 256>>>(Wh, s1, s2, m, cat,
                                                     NHEADS * NHID, ACT_ELU);
        gemm64<<<dim3(2, 64, 1), 256>>>(cat, rW, rb, bufC, NHEADS * NHID, NHID, ACT_NONE, 0, 0);
        ln_add<<<M_, NHID>>>(bufC, bufA, bufA, nullptr);
    };
    auto out_gat = [&](int sel, const unsigned* m, float* dst) {
        const float* Wptr = out_W + (size_t)sel * NHID * NHID;
        const float* aptr = out_a + (size_t)sel * 2 * NHID;
        gemm64<<<dim3(2, 64, 1), 256>>>(bufA, Wptr, nullptr, Wh, NHID, NHID, ACT_NONE, 0, 0);
        s1s2_kernel<<<dim3(M_ / 8, 1), 256>>>(Wh, aptr, s1, s2, 0);
        gat_attn<<<dim3(N_ / 32, B_, 1), 256>>>(Wh, s1, s2, m, dst, NHID, ACT_LRELU);
    };

    // ---- forward branch ----
    attn_block(0, maskp);
    attn_block(1, maskp);
    attn_block(2, maskp);
    out_gat(0, maskp, bufC);                       // bufC = h (forward output)
    copyf<<<(M_ * NHID + 255) / 256, 256>>>(bufC, hsave, bufA, M_ * NHID);

    // ---- backward branch (transposed mask) ----
    attn_block(3, maskTp);
    attn_block(4, maskTp);
    attn_block(5, maskTp);
    out_gat(1, maskTp, bufC);                      // bufC = ht

    // ---- mean over nodes + projection ----
    finalize<<<B_, 256>>>(hsave, bufC, proj_W, proj_b, out);
}